// round 15
// baseline (speedup 1.0000x reference)
#include <cuda_runtime.h>
#include <cuda_bf16.h>
#include <math.h>
#include <stdint.h>

// ---------------- Problem constants ----------------
#define BATCH 16384
#define NFEAT 39
#define EMB   16
#define HID   200
#define NPAD  208           // padded N (and K) for 16/8 tiling
#define NKSG  27            // total ksteps: L0:1, L1:13, L2:13
#define NTILE 26            // n8 tiles per layer

// ---------------- Scratch ----------------
__device__ float g_fm[BATCH * EMB];
__device__ float g_lr[BATCH];
// Weights pre-packed in mma fragment order:
// [ksg (27)][ntile (26)][lane (32)] x uint4 {bh0, bh1, bl0, bl1}
__device__ uint4 g_wfrag[NKSG * NTILE * 32];

// =====================================================================
// Helpers
// =====================================================================
__device__ __forceinline__ uint32_t smem_u32(const void* p) {
    uint32_t a;
    asm("{ .reg .u64 t; cvta.to.shared.u64 t, %1; cvt.u32.u64 %0, t; }"
        : "=r"(a) : "l"(p));
    return a;
}
__device__ __forceinline__ void ldsm4(uint32_t addr, uint32_t* r) {
    asm volatile("ldmatrix.sync.aligned.m8n8.x4.shared.b16 {%0,%1,%2,%3}, [%4];"
                 : "=r"(r[0]), "=r"(r[1]), "=r"(r[2]), "=r"(r[3]) : "r"(addr));
}
__device__ __forceinline__ void mma16816(float* c, const uint32_t* a,
                                         uint32_t b0, uint32_t b1) {
    asm volatile("mma.sync.aligned.m16n8k16.row.col.f32.bf16.bf16.f32 "
                 "{%0,%1,%2,%3}, {%4,%5,%6,%7}, {%8,%9}, {%0,%1,%2,%3};"
                 : "+f"(c[0]), "+f"(c[1]), "+f"(c[2]), "+f"(c[3])
                 : "r"(a[0]), "r"(a[1]), "r"(a[2]), "r"(a[3]),
                   "r"(b0), "r"(b1));
}
__device__ __forceinline__ void split_pack(float x0, float x1,
                                           unsigned& wh, unsigned& wl) {
    __nv_bfloat16 h0 = __float2bfloat16_rn(x0);
    __nv_bfloat16 h1 = __float2bfloat16_rn(x1);
    float r0 = x0 - __bfloat162float(h0);
    float r1 = x1 - __bfloat162float(h1);
    __nv_bfloat16 l0 = __float2bfloat16_rn(r0);
    __nv_bfloat16 l1 = __float2bfloat16_rn(r1);
    wh = ((unsigned)__bfloat16_as_ushort(h1) << 16) | __bfloat16_as_ushort(h0);
    wl = ((unsigned)__bfloat16_as_ushort(l1) << 16) | __bfloat16_as_ushort(l0);
}
__device__ __forceinline__ void bar_grp(int grp) {
    asm volatile("bar.sync %0, 128;" :: "r"(1 + grp) : "memory");
}

// =====================================================================
// Kernel 1: embedding/FM/LR (blocks 0..255, 64 rows each, high occ)
//           + weight fragment prep (blocks 256+)
// v table (64MB) is L2-resident; many warps hide L2 latency.
// =====================================================================
#define EMB_BLOCKS 256
#define PREP_ITEMS (NKSG * NTILE * 32)          // 22464
#define PREP_BLOCKS ((PREP_ITEMS + 255) / 256)  // 88

__global__ __launch_bounds__(256, 1) void embed_prep_kernel(
    const int*   __restrict__ ids,
    const float* __restrict__ vals,
    const float* __restrict__ w,
    const float* __restrict__ v,
    const float* __restrict__ w0,
    const float* __restrict__ w1,
    const float* __restrict__ w2)
{
    const int tid = threadIdx.x;
    if (blockIdx.x < EMB_BLOCKS) {
        const int t     = blockIdx.x * 256 + tid;
        const int r     = t >> 2;            // global row
        const int equad = t & 3;             // e-quad 0..3
        const int*   idp = ids  + r * NFEAT;
        const float* vp  = vals + r * NFEAT;

        float4 xv = make_float4(0.f, 0.f, 0.f, 0.f);
        float4 x2 = make_float4(0.f, 0.f, 0.f, 0.f);
        float  lrw = 0.f;
#pragma unroll 13
        for (int f = 0; f < NFEAT; ++f) {
            const int   id  = __ldg(idp + f);
            const float val = __ldg(vp + f);
            const float4 ve = __ldg((const float4*)(v + (size_t)id * EMB) + equad);
            const float t0 = val * ve.x, t1 = val * ve.y;
            const float t2 = val * ve.z, t3 = val * ve.w;
            xv.x += t0; xv.y += t1; xv.z += t2; xv.w += t3;
            x2.x += t0 * t0; x2.y += t1 * t1;
            x2.z += t2 * t2; x2.w += t3 * t3;
            if (equad == 0) lrw += __ldg(w + id) * val;
        }
        float4 fm;
        fm.x = 0.5f * (xv.x * xv.x - x2.x);
        fm.y = 0.5f * (xv.y * xv.y - x2.y);
        fm.z = 0.5f * (xv.z * xv.z - x2.z);
        fm.w = 0.5f * (xv.w * xv.w - x2.w);
        *((float4*)(g_fm + (size_t)r * EMB) + equad) = fm;
        if (equad == 0) g_lr[r] = lrw;
    } else {
        const int g = (blockIdx.x - EMB_BLOCKS) * 256 + tid;
        if (g >= PREP_ITEMS) return;
        const int ksg   = g / (NTILE * 32);
        const int rem   = g - ksg * (NTILE * 32);
        const int ntile = rem >> 5;
        const int lane  = rem & 31;
        const int l  = (ksg == 0) ? 0 : (ksg <= 13) ? 1 : 2;
        const int s  = (ksg == 0) ? 0 : (ksg <= 13) ? (ksg - 1) : (ksg - 14);
        const int Kl = (l == 0) ? EMB : HID;
        const float* W = (l == 0) ? w0 : (l == 1) ? w1 : w2;

        const int n  = ntile * 8 + (lane >> 2);
        const int k0 = s * 16 + (lane & 3) * 2;

        float e0 = 0.f, e1 = 0.f, e2 = 0.f, e3 = 0.f;
        if (n < HID) {
            if (k0     < Kl) e0 = __ldg(W + (size_t)k0       * HID + n);
            if (k0 + 1 < Kl) e1 = __ldg(W + (size_t)(k0 + 1) * HID + n);
            if (k0 + 8 < Kl) e2 = __ldg(W + (size_t)(k0 + 8) * HID + n);
            if (k0 + 9 < Kl) e3 = __ldg(W + (size_t)(k0 + 9) * HID + n);
        }
        uint4 o;
        split_pack(e0, e1, o.x, o.z);
        split_pack(e2, e3, o.y, o.w);
        g_wfrag[g] = o;
    }
}

// =====================================================================
// Kernel 2: split-bf16 mma.sync MLP + sigmoid (reads g_fm/g_lr).
// 64 rows/CTA, 256 threads, 2 CTAs/SM.
// Warp tile: 32 rows (2 m16) x QN n8-tiles (quarters {7,7,6,6}).
// K-loops FULLY UNROLLED so ptxas can pipeline B-frag LDGs across
// kstep boundaries (registers freed by removing the embed phase).
// =====================================================================
#define NTH2 256
#define ROWS 64
#define APB  464                 // As row pitch in bytes (208 bf16 + pad)
#define AS_H 0
#define AS_L (ROWS * APB)                    // 29696
#define BIAS_O (2 * ROWS * APB)              // 59392
#define RSUM_O (BIAS_O + 3 * NPAD * 4)       // 61888
#define SMEM_TOT (RSUM_O + ROWS * 4)         // 62144

template<int QN, int KSTEPS>
__device__ __forceinline__ void do_layer(
    float (&acc)[2][7][4],
    const uint32_t aH0, const uint32_t aL0, const uint32_t akofs,
    const int ksbase, const int qtile0, const int lane)
{
#pragma unroll
    for (int m = 0; m < 2; ++m)
#pragma unroll
        for (int t = 0; t < QN; ++t)
#pragma unroll
            for (int q = 0; q < 4; ++q) acc[m][t][q] = 0.f;

#pragma unroll
    for (int ks = 0; ks < KSTEPS; ++ks) {
        const uint32_t ko = (uint32_t)(ks * 16) + akofs;
        uint32_t ah0[4], al0[4], ah1[4], al1[4];
        ldsm4(aH0 + ko * 2, ah0);
        ldsm4(aL0 + ko * 2, al0);
        ldsm4(aH0 + 16 * APB + ko * 2, ah1);
        ldsm4(aL0 + 16 * APB + ko * 2, al1);
        const uint4* bp = g_wfrag
            + ((size_t)(ksbase + ks) * NTILE + qtile0) * 32 + lane;
#pragma unroll
        for (int nt = 0; nt < QN; ++nt) {
            const uint4 f = __ldg(bp + nt * 32);
            mma16816(acc[0][nt], ah0, f.x, f.y);
            mma16816(acc[0][nt], ah0, f.z, f.w);
            mma16816(acc[0][nt], al0, f.x, f.y);
            mma16816(acc[1][nt], ah1, f.x, f.y);
            mma16816(acc[1][nt], ah1, f.z, f.w);
            mma16816(acc[1][nt], al1, f.x, f.y);
        }
    }
}

template<int QN>
__device__ __forceinline__ void epi_store(
    float (&acc)[2][7][4], char* smem, const float* __restrict__ bias,
    const int rowgrp, const int qtile0, const int lane)
{
#pragma unroll
    for (int m = 0; m < 2; ++m) {
        const int r1 = rowgrp * 32 + m * 16 + (lane >> 2);
#pragma unroll
        for (int nt = 0; nt < QN; ++nt) {
            const int n = (qtile0 + nt) * 8 + 2 * (lane & 3);
            const float bb0 = bias[n];
            const float bb1 = bias[n + 1];
            unsigned wh, wl;
            split_pack(fmaxf(acc[m][nt][0] + bb0, 0.f),
                       fmaxf(acc[m][nt][1] + bb1, 0.f), wh, wl);
            *(unsigned*)(smem + AS_H + r1 * APB + 2 * n) = wh;
            *(unsigned*)(smem + AS_L + r1 * APB + 2 * n) = wl;
            split_pack(fmaxf(acc[m][nt][2] + bb0, 0.f),
                       fmaxf(acc[m][nt][3] + bb1, 0.f), wh, wl);
            *(unsigned*)(smem + AS_H + (r1 + 8) * APB + 2 * n) = wh;
            *(unsigned*)(smem + AS_L + (r1 + 8) * APB + 2 * n) = wl;
        }
    }
}

template<int QN>
__device__ __forceinline__ void mlp_body(
    char* smem, const uint32_t SB,
    const float* __restrict__ bias_s, float* __restrict__ rsum_s,
    const int rowgrp, const int qtile0, const int lane)
{
    float acc[2][7][4];

    const uint32_t arow  = (uint32_t)(rowgrp * 32 + (lane & 15));
    const uint32_t akofs = (uint32_t)((lane >> 4) << 3);
    const uint32_t aH0 = SB + AS_H + arow * APB;
    const uint32_t aL0 = SB + AS_L + arow * APB;

    // Layer 0 (K=16)
    do_layer<QN, 1>(acc, aH0, aL0, akofs, 0, qtile0, lane);
    bar_grp(rowgrp);
    epi_store<QN>(acc, smem, bias_s, rowgrp, qtile0, lane);
    bar_grp(rowgrp);

    // Layer 1 (K=208)
    do_layer<QN, 13>(acc, aH0, aL0, akofs, 1, qtile0, lane);
    bar_grp(rowgrp);
    epi_store<QN>(acc, smem, bias_s + NPAD, rowgrp, qtile0, lane);
    bar_grp(rowgrp);

    // Layer 2 (K=208) + row sums
    do_layer<QN, 13>(acc, aH0, aL0, akofs, 14, qtile0, lane);
    float rs[2][2] = {{0.f, 0.f}, {0.f, 0.f}};
    const float* bias = bias_s + 2 * NPAD;
#pragma unroll
    for (int m = 0; m < 2; ++m)
#pragma unroll
        for (int nt = 0; nt < QN; ++nt) {
            const int n = (qtile0 + nt) * 8 + 2 * (lane & 3);
            const float bb0 = bias[n];
            const float bb1 = bias[n + 1];
            rs[m][0] += fmaxf(acc[m][nt][0] + bb0, 0.f)
                      + fmaxf(acc[m][nt][1] + bb1, 0.f);
            rs[m][1] += fmaxf(acc[m][nt][2] + bb0, 0.f)
                      + fmaxf(acc[m][nt][3] + bb1, 0.f);
        }
#pragma unroll
    for (int m = 0; m < 2; ++m)
#pragma unroll
        for (int h = 0; h < 2; ++h) {
            rs[m][h] += __shfl_xor_sync(0xffffffffu, rs[m][h], 1);
            rs[m][h] += __shfl_xor_sync(0xffffffffu, rs[m][h], 2);
        }
    if ((lane & 3) == 0) {
        const int rb = rowgrp * 32 + (lane >> 2);
        atomicAdd(&rsum_s[rb],      rs[0][0]);
        atomicAdd(&rsum_s[rb + 8],  rs[0][1]);
        atomicAdd(&rsum_s[rb + 16], rs[1][0]);
        atomicAdd(&rsum_s[rb + 24], rs[1][1]);
    }
}

__global__ __launch_bounds__(NTH2, 2) void mlp_kernel(
    const float* __restrict__ b0,
    const float* __restrict__ b1,
    const float* __restrict__ b2,
    const float* __restrict__ bglob,
    float*       __restrict__ out)
{
    extern __shared__ char smem[];
    const uint32_t SB = smem_u32(smem);
    float* bias_s = (float*)(smem + BIAS_O);
    float* rsum_s = (float*)(smem + RSUM_O);

    const int tid    = threadIdx.x;
    const int wid    = tid >> 5;
    const int lane   = tid & 31;
    const int rowgrp = wid >> 2;             // 0..1 (32 rows each)
    const int nq     = wid & 3;              // n-quarter
    const int row0   = blockIdx.x * ROWS;
    const int qtile0 = (nq == 0) ? 0 : (nq == 1) ? 7 : (nq == 2) ? 14 : 20;

    // ---- init: bias + rsum + L0 activations from g_fm ----
    for (int i = tid; i < 3 * NPAD; i += NTH2) {
        const int l = i / NPAD, n = i - l * NPAD;
        const float* bp = (l == 0) ? b0 : (l == 1) ? b1 : b2;
        bias_s[i] = (n < HID) ? __ldg(bp + n) : 0.f;
    }
    if (tid < ROWS) rsum_s[tid] = 0.f;
    {
        const int r     = tid >> 2;          // 0..63 row in CTA
        const int equad = tid & 3;
        const float4 fm = __ldg((const float4*)(g_fm + (size_t)(row0 + r) * EMB)
                                + equad);
        unsigned h0, l0, h1, l1;
        split_pack(fm.x, fm.y, h0, l0);
        split_pack(fm.z, fm.w, h1, l1);
        *(uint2*)(smem + AS_H + r * APB + equad * 8) = make_uint2(h0, h1);
        *(uint2*)(smem + AS_L + r * APB + equad * 8) = make_uint2(l0, l1);
    }
    __syncthreads();        // the only CTA-wide barrier

    // ---- MLP ----
    if (nq < 2) mlp_body<7>(smem, SB, bias_s, rsum_s, rowgrp, qtile0, lane);
    else        mlp_body<6>(smem, SB, bias_s, rsum_s, rowgrp, qtile0, lane);

    bar_grp(rowgrp);

    if (nq == 0) {
        const int r  = rowgrp * 32 + lane;
        const int gr = row0 + r;
        const float x = __ldg(&((const float*)g_lr)[gr]) + __ldg(bglob)
                      + rsum_s[r];
        out[gr] = 1.f / (1.f + expf(-x));
    }
}

// =====================================================================
// Launch
// =====================================================================
extern "C" void kernel_launch(void* const* d_in, const int* in_sizes, int n_in,
                              void* d_out, int out_size)
{
    const int*   feat_ids  = (const int*)  d_in[0];
    const float* feat_vals = (const float*)d_in[1];
    const float* w         = (const float*)d_in[2];
    const float* v         = (const float*)d_in[3];
    const float* b         = (const float*)d_in[4];
    const float* w0        = (const float*)d_in[5];
    const float* b0        = (const float*)d_in[6];
    const float* w1        = (const float*)d_in[7];
    const float* b1        = (const float*)d_in[8];
    const float* w2        = (const float*)d_in[9];
    const float* b2        = (const float*)d_in[10];
    float* out = (float*)d_out;

    embed_prep_kernel<<<EMB_BLOCKS + PREP_BLOCKS, 256>>>(
        feat_ids, feat_vals, w, v, w0, w1, w2);

    static bool attr_set = false;
    if (!attr_set) {
        cudaFuncSetAttribute(mlp_kernel,
                             cudaFuncAttributeMaxDynamicSharedMemorySize,
                             SMEM_TOT);
        attr_set = true;
    }
    mlp_kernel<<<BATCH / ROWS, NTH2, SMEM_TOT>>>(b0, b1, b2, b, out);
}

// round 17
// speedup vs baseline: 1.1767x; 1.1767x over previous
#include <cuda_runtime.h>
#include <cuda_fp16.h>
#include <math.h>
#include <stdint.h>

// ---------------- Problem constants ----------------
#define BATCH 16384
#define NFEAT 39
#define EMB   16
#define HID   200
#define NPAD  208           // padded N (and K) for 16/8 tiling
#define NKSG  27            // total ksteps: L0:1, L1:13, L2:13
#define NTILE 26            // n8 tiles per layer

// ---------------- Scratch ----------------
__device__ float g_fm[BATCH * EMB];
__device__ float g_lr[BATCH];
// Weights pre-packed in mma fragment order, SINGLE fp16:
// [ksg (27)][ntile (26)][lane (32)] x uint2 {b0, b1}
__device__ uint2 g_wfrag[NKSG * NTILE * 32];

// =====================================================================
// Helpers
// =====================================================================
__device__ __forceinline__ uint32_t smem_u32(const void* p) {
    uint32_t a;
    asm("{ .reg .u64 t; cvta.to.shared.u64 t, %1; cvt.u32.u64 %0, t; }"
        : "=r"(a) : "l"(p));
    return a;
}
__device__ __forceinline__ void ldsm4(uint32_t addr, uint32_t* r) {
    asm volatile("ldmatrix.sync.aligned.m8n8.x4.shared.b16 {%0,%1,%2,%3}, [%4];"
                 : "=r"(r[0]), "=r"(r[1]), "=r"(r[2]), "=r"(r[3]) : "r"(addr));
}
__device__ __forceinline__ void mma16816(float* c, const uint32_t* a,
                                         uint32_t b0, uint32_t b1) {
    asm volatile("mma.sync.aligned.m16n8k16.row.col.f32.f16.f16.f32 "
                 "{%0,%1,%2,%3}, {%4,%5,%6,%7}, {%8,%9}, {%0,%1,%2,%3};"
                 : "+f"(c[0]), "+f"(c[1]), "+f"(c[2]), "+f"(c[3])
                 : "r"(a[0]), "r"(a[1]), "r"(a[2]), "r"(a[3]),
                   "r"(b0), "r"(b1));
}
__device__ __forceinline__ unsigned pack_f16(float x0, float x1) {
    __half h0 = __float2half_rn(x0);
    __half h1 = __float2half_rn(x1);
    return ((unsigned)__half_as_ushort(h1) << 16) | __half_as_ushort(h0);
}
// Split a f32 pair into fp16 hi and fp16 lo (residual) packed words.
__device__ __forceinline__ void split_pack_f16(float x0, float x1,
                                               unsigned& wh, unsigned& wl) {
    __half h0 = __float2half_rn(x0);
    __half h1 = __float2half_rn(x1);
    float r0 = x0 - __half2float(h0);
    float r1 = x1 - __half2float(h1);
    wh = ((unsigned)__half_as_ushort(h1) << 16) | __half_as_ushort(h0);
    wl = pack_f16(r0, r1);
}
__device__ __forceinline__ void bar_grp(int grp) {
    asm volatile("bar.sync %0, 128;" :: "r"(1 + grp) : "memory");
}

// =====================================================================
// Kernel 1: embedding/FM/LR (blocks 0..255) + weight prep (blocks 256+)
// =====================================================================
#define EMB_BLOCKS 256
#define PREP_ITEMS (NKSG * NTILE * 32)          // 22464
#define PREP_BLOCKS ((PREP_ITEMS + 255) / 256)  // 88

__global__ __launch_bounds__(256, 1) void embed_prep_kernel(
    const int*   __restrict__ ids,
    const float* __restrict__ vals,
    const float* __restrict__ w,
    const float* __restrict__ v,
    const float* __restrict__ w0,
    const float* __restrict__ w1,
    const float* __restrict__ w2)
{
    const int tid = threadIdx.x;
    if (blockIdx.x < EMB_BLOCKS) {
        const int t     = blockIdx.x * 256 + tid;
        const int r     = t >> 2;            // global row
        const int equad = t & 3;             // e-quad 0..3
        const int*   idp = ids  + r * NFEAT;
        const float* vp  = vals + r * NFEAT;

        float4 xv = make_float4(0.f, 0.f, 0.f, 0.f);
        float4 x2 = make_float4(0.f, 0.f, 0.f, 0.f);
        float  lrw = 0.f;
#pragma unroll 13
        for (int f = 0; f < NFEAT; ++f) {
            const int   id  = __ldg(idp + f);
            const float val = __ldg(vp + f);
            const float4 ve = __ldg((const float4*)(v + (size_t)id * EMB) + equad);
            const float t0 = val * ve.x, t1 = val * ve.y;
            const float t2 = val * ve.z, t3 = val * ve.w;
            xv.x += t0; xv.y += t1; xv.z += t2; xv.w += t3;
            x2.x += t0 * t0; x2.y += t1 * t1;
            x2.z += t2 * t2; x2.w += t3 * t3;
            if (equad == 0) lrw += __ldg(w + id) * val;
        }
        float4 fm;
        fm.x = 0.5f * (xv.x * xv.x - x2.x);
        fm.y = 0.5f * (xv.y * xv.y - x2.y);
        fm.z = 0.5f * (xv.z * xv.z - x2.z);
        fm.w = 0.5f * (xv.w * xv.w - x2.w);
        *((float4*)(g_fm + (size_t)r * EMB) + equad) = fm;
        if (equad == 0) g_lr[r] = lrw;
    } else {
        const int g = (blockIdx.x - EMB_BLOCKS) * 256 + tid;
        if (g >= PREP_ITEMS) return;
        const int ksg   = g / (NTILE * 32);
        const int rem   = g - ksg * (NTILE * 32);
        const int ntile = rem >> 5;
        const int lane  = rem & 31;
        const int l  = (ksg == 0) ? 0 : (ksg <= 13) ? 1 : 2;
        const int s  = (ksg == 0) ? 0 : (ksg <= 13) ? (ksg - 1) : (ksg - 14);
        const int Kl = (l == 0) ? EMB : HID;
        const float* W = (l == 0) ? w0 : (l == 1) ? w1 : w2;

        const int n  = ntile * 8 + (lane >> 2);
        const int k0 = s * 16 + (lane & 3) * 2;

        float e0 = 0.f, e1 = 0.f, e2 = 0.f, e3 = 0.f;
        if (n < HID) {
            if (k0     < Kl) e0 = __ldg(W + (size_t)k0       * HID + n);
            if (k0 + 1 < Kl) e1 = __ldg(W + (size_t)(k0 + 1) * HID + n);
            if (k0 + 8 < Kl) e2 = __ldg(W + (size_t)(k0 + 8) * HID + n);
            if (k0 + 9 < Kl) e3 = __ldg(W + (size_t)(k0 + 9) * HID + n);
        }
        uint2 o;
        o.x = pack_f16(e0, e1);
        o.y = pack_f16(e2, e3);
        g_wfrag[g] = o;
    }
}

// =====================================================================
// Kernel 2: split-A fp16 mma.sync MLP + sigmoid (reads g_fm/g_lr).
// D = ah*bh + al*bh  (B single fp16, A split fp16 hi+lo): 2 MMAs per
// logical MMA instead of 3.
// 64 rows/CTA, 256 threads, 2 CTAs/SM.
// Warp tile: 32 rows (2 m16) x QN n8-tiles (quarters {7,7,6,6}).
// =====================================================================
#define NTH2 256
#define ROWS 64
#define APB  464                 // As row pitch in bytes (208 fp16 + pad)
#define AS_H 0
#define AS_L (ROWS * APB)                    // 29696
#define BIAS_O (2 * ROWS * APB)              // 59392
#define RSUM_O (BIAS_O + 3 * NPAD * 4)       // 61888
#define SMEM_TOT (RSUM_O + ROWS * 4)         // 62144

template<int QN, int KSTEPS>
__device__ __forceinline__ void do_layer(
    float (&acc)[2][7][4],
    const uint32_t aH0, const uint32_t aL0, const uint32_t akofs,
    const int ksbase, const int qtile0, const int lane)
{
#pragma unroll
    for (int m = 0; m < 2; ++m)
#pragma unroll
        for (int t = 0; t < QN; ++t)
#pragma unroll
            for (int q = 0; q < 4; ++q) acc[m][t][q] = 0.f;

#pragma unroll
    for (int ks = 0; ks < KSTEPS; ++ks) {
        const uint32_t ko = (uint32_t)(ks * 16) + akofs;
        uint32_t ah0[4], al0[4], ah1[4], al1[4];
        ldsm4(aH0 + ko * 2, ah0);
        ldsm4(aL0 + ko * 2, al0);
        ldsm4(aH0 + 16 * APB + ko * 2, ah1);
        ldsm4(aL0 + 16 * APB + ko * 2, al1);
        const uint2* bp = g_wfrag
            + ((size_t)(ksbase + ks) * NTILE + qtile0) * 32 + lane;
#pragma unroll
        for (int nt = 0; nt < QN; ++nt) {
            const uint2 f = __ldg(bp + nt * 32);
            mma16816(acc[0][nt], ah0, f.x, f.y);
            mma16816(acc[0][nt], al0, f.x, f.y);
            mma16816(acc[1][nt], ah1, f.x, f.y);
            mma16816(acc[1][nt], al1, f.x, f.y);
        }
    }
}

template<int QN>
__device__ __forceinline__ void epi_store(
    float (&acc)[2][7][4], char* smem, const float* __restrict__ bias,
    const int rowgrp, const int qtile0, const int lane)
{
#pragma unroll
    for (int m = 0; m < 2; ++m) {
        const int r1 = rowgrp * 32 + m * 16 + (lane >> 2);
#pragma unroll
        for (int nt = 0; nt < QN; ++nt) {
            const int n = (qtile0 + nt) * 8 + 2 * (lane & 3);
            const float bb0 = bias[n];
            const float bb1 = bias[n + 1];
            unsigned wh, wl;
            split_pack_f16(fmaxf(acc[m][nt][0] + bb0, 0.f),
                           fmaxf(acc[m][nt][1] + bb1, 0.f), wh, wl);
            *(unsigned*)(smem + AS_H + r1 * APB + 2 * n) = wh;
            *(unsigned*)(smem + AS_L + r1 * APB + 2 * n) = wl;
            split_pack_f16(fmaxf(acc[m][nt][2] + bb0, 0.f),
                           fmaxf(acc[m][nt][3] + bb1, 0.f), wh, wl);
            *(unsigned*)(smem + AS_H + (r1 + 8) * APB + 2 * n) = wh;
            *(unsigned*)(smem + AS_L + (r1 + 8) * APB + 2 * n) = wl;
        }
    }
}

template<int QN>
__device__ __forceinline__ void mlp_body(
    char* smem, const uint32_t SB,
    const float* __restrict__ bias_s, float* __restrict__ rsum_s,
    const int rowgrp, const int qtile0, const int lane)
{
    float acc[2][7][4];

    const uint32_t arow  = (uint32_t)(rowgrp * 32 + (lane & 15));
    const uint32_t akofs = (uint32_t)((lane >> 4) << 3);
    const uint32_t aH0 = SB + AS_H + arow * APB;
    const uint32_t aL0 = SB + AS_L + arow * APB;

    // Layer 0 (K=16)
    do_layer<QN, 1>(acc, aH0, aL0, akofs, 0, qtile0, lane);
    bar_grp(rowgrp);
    epi_store<QN>(acc, smem, bias_s, rowgrp, qtile0, lane);
    bar_grp(rowgrp);

    // Layer 1 (K=208)
    do_layer<QN, 13>(acc, aH0, aL0, akofs, 1, qtile0, lane);
    bar_grp(rowgrp);
    epi_store<QN>(acc, smem, bias_s + NPAD, rowgrp, qtile0, lane);
    bar_grp(rowgrp);

    // Layer 2 (K=208) + row sums
    do_layer<QN, 13>(acc, aH0, aL0, akofs, 14, qtile0, lane);
    float rs[2][2] = {{0.f, 0.f}, {0.f, 0.f}};
    const float* bias = bias_s + 2 * NPAD;
#pragma unroll
    for (int m = 0; m < 2; ++m)
#pragma unroll
        for (int nt = 0; nt < QN; ++nt) {
            const int n = (qtile0 + nt) * 8 + 2 * (lane & 3);
            const float bb0 = bias[n];
            const float bb1 = bias[n + 1];
            rs[m][0] += fmaxf(acc[m][nt][0] + bb0, 0.f)
                      + fmaxf(acc[m][nt][1] + bb1, 0.f);
            rs[m][1] += fmaxf(acc[m][nt][2] + bb0, 0.f)
                      + fmaxf(acc[m][nt][3] + bb1, 0.f);
        }
#pragma unroll
    for (int m = 0; m < 2; ++m)
#pragma unroll
        for (int h = 0; h < 2; ++h) {
            rs[m][h] += __shfl_xor_sync(0xffffffffu, rs[m][h], 1);
            rs[m][h] += __shfl_xor_sync(0xffffffffu, rs[m][h], 2);
        }
    if ((lane & 3) == 0) {
        const int rb = rowgrp * 32 + (lane >> 2);
        atomicAdd(&rsum_s[rb],      rs[0][0]);
        atomicAdd(&rsum_s[rb + 8],  rs[0][1]);
        atomicAdd(&rsum_s[rb + 16], rs[1][0]);
        atomicAdd(&rsum_s[rb + 24], rs[1][1]);
    }
}

__global__ __launch_bounds__(NTH2, 2) void mlp_kernel(
    const float* __restrict__ b0,
    const float* __restrict__ b1,
    const float* __restrict__ b2,
    const float* __restrict__ bglob,
    float*       __restrict__ out)
{
    extern __shared__ char smem[];
    const uint32_t SB = smem_u32(smem);
    float* bias_s = (float*)(smem + BIAS_O);
    float* rsum_s = (float*)(smem + RSUM_O);

    const int tid    = threadIdx.x;
    const int wid    = tid >> 5;
    const int lane   = tid & 31;
    const int rowgrp = wid >> 2;             // 0..1 (32 rows each)
    const int nq     = wid & 3;              // n-quarter
    const int row0   = blockIdx.x * ROWS;
    const int qtile0 = (nq == 0) ? 0 : (nq == 1) ? 7 : (nq == 2) ? 14 : 20;

    // ---- init: bias + rsum + L0 activations from g_fm ----
    for (int i = tid; i < 3 * NPAD; i += NTH2) {
        const int l = i / NPAD, n = i - l * NPAD;
        const float* bp = (l == 0) ? b0 : (l == 1) ? b1 : b2;
        bias_s[i] = (n < HID) ? __ldg(bp + n) : 0.f;
    }
    if (tid < ROWS) rsum_s[tid] = 0.f;
    {
        const int r     = tid >> 2;          // 0..63 row in CTA
        const int equad = tid & 3;
        const float4 fm = __ldg((const float4*)(g_fm + (size_t)(row0 + r) * EMB)
                                + equad);
        unsigned h0, l0, h1, l1;
        split_pack_f16(fm.x, fm.y, h0, l0);
        split_pack_f16(fm.z, fm.w, h1, l1);
        *(uint2*)(smem + AS_H + r * APB + equad * 8) = make_uint2(h0, h1);
        *(uint2*)(smem + AS_L + r * APB + equad * 8) = make_uint2(l0, l1);
    }
    __syncthreads();        // the only CTA-wide barrier

    // ---- MLP ----
    if (nq < 2) mlp_body<7>(smem, SB, bias_s, rsum_s, rowgrp, qtile0, lane);
    else        mlp_body<6>(smem, SB, bias_s, rsum_s, rowgrp, qtile0, lane);

    bar_grp(rowgrp);

    if (nq == 0) {
        const int r  = rowgrp * 32 + lane;
        const int gr = row0 + r;
        const float x = __ldg(&((const float*)g_lr)[gr]) + __ldg(bglob)
                      + rsum_s[r];
        out[gr] = 1.f / (1.f + expf(-x));
    }
}

// =====================================================================
// Launch
// =====================================================================
extern "C" void kernel_launch(void* const* d_in, const int* in_sizes, int n_in,
                              void* d_out, int out_size)
{
    const int*   feat_ids  = (const int*)  d_in[0];
    const float* feat_vals = (const float*)d_in[1];
    const float* w         = (const float*)d_in[2];
    const float* v         = (const float*)d_in[3];
    const float* b         = (const float*)d_in[4];
    const float* w0        = (const float*)d_in[5];
    const float* b0        = (const float*)d_in[6];
    const float* w1        = (const float*)d_in[7];
    const float* b1        = (const float*)d_in[8];
    const float* w2        = (const float*)d_in[9];
    const float* b2        = (const float*)d_in[10];
    float* out = (float*)d_out;

    embed_prep_kernel<<<EMB_BLOCKS + PREP_BLOCKS, 256>>>(
        feat_ids, feat_vals, w, v, w0, w1, w2);

    static bool attr_set = false;
    if (!attr_set) {
        cudaFuncSetAttribute(mlp_kernel,
                             cudaFuncAttributeMaxDynamicSharedMemorySize,
                             SMEM_TOT);
        attr_set = true;
    }
    mlp_kernel<<<BATCH / ROWS, NTH2, SMEM_TOT>>>(b0, b1, b2, b, out);
}